// round 3
// baseline (speedup 1.0000x reference)
#include <cuda_runtime.h>
#include <cuda_fp16.h>
#include <math.h>

#define BB 16
#define HH 12
#define NN 784
#define NROWS (BB * NN)        // 12544
#define NSQ (NN * NN)          // 614656
#define NBLK NROWS

// Device-global scratch (allocation is forbidden; __device__ globals are allowed)
__device__ __half g_scratch[(size_t)BB * NSQ];   // exp(x - rowmax), ~19.7 MB
__device__ float2 g_rowstats[NROWS];             // (rowmax, rowsumexp)
__device__ float  g_rowscale[NROWS];             // exp(rowmax - gmax) / sum_b
__device__ int    g_count;                       // zero-init; self-resets each call

// ---------------------------------------------------------------------------
// k_agg: one block per (b,i). 384 threads = 12 warps, warp w stages head w's
// row in SMEM + computes its rowsum. agg[l] = sum_h m[h][l]*rowsum[h] kept in
// registers; per-row max + exp + expsum computed in-block; exp written as fp16.
// The LAST block to finish (atomic counter) performs the per-batch softmax
// combine (gmax, 1/sum, per-row scales) warp-parallel, then resets the counter.
// Deterministic: combine result is order-independent; counter returns to 0.
// ---------------------------------------------------------------------------
__global__ __launch_bounds__(384) void k_agg(const float* __restrict__ m) {
    __shared__ float sm[HH * NN];   // 37632 B
    __shared__ float rs[HH];
    __shared__ float red[HH];
    __shared__ float s_bcast;
    __shared__ int   s_last;

    const int bi = blockIdx.x;          // b*NN + i
    const int b  = bi / NN;
    const int i  = bi - b * NN;
    const int t    = threadIdx.x;
    const int w    = t >> 5;
    const int lane = t & 31;

    // stage head-w row (196 float4s, streaming) + rowsum
    const float4* row = (const float4*)(m + ((size_t)(b * HH + w) * NN + i) * NN);
    float4* smrow = (float4*)(sm + w * NN);
    float s = 0.f;
    #pragma unroll
    for (int j = lane; j < NN / 4; j += 32) {
        float4 v = __ldcs(row + j);
        smrow[j] = v;
        s += (v.x + v.y) + (v.z + v.w);
    }
    #pragma unroll
    for (int o = 16; o; o >>= 1) s += __shfl_xor_sync(0xffffffffu, s, o);
    if (lane == 0) rs[w] = s;
    __syncthreads();

    float rr[HH];
    #pragma unroll
    for (int h = 0; h < HH; h++) rr[h] = rs[h];

    // aggregated row values in registers
    float a0 = 0.f, a1 = 0.f, a2 = 0.f;
    #pragma unroll
    for (int h = 0; h < HH; h++) {
        a0 = fmaf(sm[h * NN + t],       rr[h], a0);
        a1 = fmaf(sm[h * NN + t + 384], rr[h], a1);
    }
    if (t < 16) {
        #pragma unroll
        for (int h = 0; h < HH; h++) a2 = fmaf(sm[h * NN + t + 768], rr[h], a2);
    }

    // row max (block reduce)
    float mx = fmaxf(a0, a1);
    if (t < 16) mx = fmaxf(mx, a2);
    #pragma unroll
    for (int o = 16; o; o >>= 1) mx = fmaxf(mx, __shfl_xor_sync(0xffffffffu, mx, o));
    if (lane == 0) red[w] = mx;
    __syncthreads();
    if (t == 0) {
        float M = red[0];
        #pragma unroll
        for (int h = 1; h < HH; h++) M = fmaxf(M, red[h]);
        s_bcast = M;
    }
    __syncthreads();
    const float rowmax = s_bcast;

    // exp + fp16 store + row expsum
    __half* srow = g_scratch + (size_t)bi * NN;
    float e0 = expf(a0 - rowmax);
    float e1 = expf(a1 - rowmax);
    srow[t]       = __float2half_rn(e0);
    srow[t + 384] = __float2half_rn(e1);
    float sume = e0 + e1;
    if (t < 16) {
        float e2 = expf(a2 - rowmax);
        srow[t + 768] = __float2half_rn(e2);
        sume += e2;
    }
    #pragma unroll
    for (int o = 16; o; o >>= 1) sume += __shfl_xor_sync(0xffffffffu, sume, o);
    if (lane == 0) red[w] = sume;
    __syncthreads();
    if (t == 0) {
        float S = 0.f;
        #pragma unroll
        for (int h = 0; h < HH; h++) S += red[h];
        g_rowstats[bi] = make_float2(rowmax, S);
        __threadfence();                       // publish rowstats before counting
        int c = atomicAdd(&g_count, 1);
        s_last = (c == NBLK - 1);
    }
    __syncthreads();
    if (!s_last) return;

    // ---- last block: per-batch combine, warp-parallel ----
    if (t == 0) { g_count = 0; __threadfence(); }
    for (int bb = w; bb < BB; bb += HH) {
        const float2* st = g_rowstats + bb * NN;
        // phase 1: gmax
        float gm = -1e30f;
        for (int r = lane; r < NN; r += 32) gm = fmaxf(gm, __ldcg(&st[r].x));
        #pragma unroll
        for (int o = 16; o; o >>= 1) gm = fmaxf(gm, __shfl_xor_sync(0xffffffffu, gm, o));
        // phase 2: sum = sum_r rowsumexp_r * exp(rowmax_r - gmax)
        float ss = 0.f;
        for (int r = lane; r < NN; r += 32) {
            float rm = __ldcg(&st[r].x);
            float rv = __ldcg(&st[r].y);
            ss += rv * expf(rm - gm);
        }
        #pragma unroll
        for (int o = 16; o; o >>= 1) ss += __shfl_xor_sync(0xffffffffu, ss, o);
        const float inv = 1.f / ss;
        // phase 3: per-row scale
        for (int r = lane; r < NN; r += 32)
            g_rowscale[bb * NN + r] = expf(__ldcg(&st[r].x) - gm) * inv;
    }
}

// ---------------------------------------------------------------------------
// k_norm: out[bi][l] = half2float(scratch[bi][l]) * rowscale[bi]
// Vectorized: 8 halves (int4) in -> 2 float4 out per thread.
// Total int4 = 16*614656/8 = 1,229,312 = 4802 blocks * 256 exactly.
// ---------------------------------------------------------------------------
__global__ __launch_bounds__(256) void k_norm(float* __restrict__ out) {
    const int j = blockIdx.x * 256 + threadIdx.x;   // int4 index
    const int row = j / 98;                          // 98 int4 per row (784/8)
    const float sc = g_rowscale[row];

    int4 v = __ldcs(((const int4*)g_scratch) + j);
    float2 f0 = __half22float2(*(__half2*)&v.x);
    float2 f1 = __half22float2(*(__half2*)&v.y);
    float2 f2 = __half22float2(*(__half2*)&v.z);
    float2 f3 = __half22float2(*(__half2*)&v.w);

    float4 o0 = make_float4(f0.x * sc, f0.y * sc, f1.x * sc, f1.y * sc);
    float4 o1 = make_float4(f2.x * sc, f2.y * sc, f3.x * sc, f3.y * sc);
    __stcs(((float4*)out) + 2 * j,     o0);
    __stcs(((float4*)out) + 2 * j + 1, o1);
}

// ---------------------------------------------------------------------------
extern "C" void kernel_launch(void* const* d_in, const int* in_sizes, int n_in,
                              void* d_out, int out_size) {
    const float* m = (const float*)d_in[0];
    float* out = (float*)d_out;

    k_agg<<<NBLK, 384>>>(m);
    k_norm<<<4802, 256>>>(out);
}

// round 4
// speedup vs baseline: 1.1528x; 1.1528x over previous
#include <cuda_runtime.h>
#include <cuda_fp16.h>
#include <math.h>

#define BB 16
#define HH 12
#define NN 784
#define NROWS (BB * NN)        // 12544
#define NSQ (NN * NN)          // 614656
#define NCHUNK (NROWS * NN / 8) // total int4 chunks in scratch = 1229312

// Device-global scratch (allocation is forbidden; __device__ globals are allowed)
__device__ __half g_scratch[(size_t)BB * NSQ];   // exp(x - rowmax), ~19.7 MB
__device__ float2 g_rowstats[NROWS];             // (rowmax, rowsumexp)
__device__ float  g_rowscale[NROWS];             // exp(rowmax - gmax) / sum_b

// ---------------------------------------------------------------------------
// k_agg: one block per (b,i). 384 threads = 12 warps, warp w stages head w's
// row in SMEM + computes its rowsum. agg[l] = sum_h m[h][l]*rowsum[h] kept in
// registers; per-row max + exp + expsum computed in-block; exp written fp16.
// (R2-proven version: no cache hints, no fences, no atomics.)
// ---------------------------------------------------------------------------
__global__ __launch_bounds__(384) void k_agg(const float* __restrict__ m) {
    __shared__ float sm[HH * NN];   // 37632 B
    __shared__ float rs[HH];
    __shared__ float red[HH];
    __shared__ float s_bcast;

    const int bi = blockIdx.x;          // b*NN + i
    const int b  = bi / NN;
    const int i  = bi - b * NN;
    const int t    = threadIdx.x;
    const int w    = t >> 5;
    const int lane = t & 31;

    const float4* row = (const float4*)(m + ((size_t)(b * HH + w) * NN + i) * NN);
    float4* smrow = (float4*)(sm + w * NN);
    float s = 0.f;
    #pragma unroll
    for (int j = lane; j < NN / 4; j += 32) {
        float4 v = row[j];
        smrow[j] = v;
        s += (v.x + v.y) + (v.z + v.w);
    }
    #pragma unroll
    for (int o = 16; o; o >>= 1) s += __shfl_xor_sync(0xffffffffu, s, o);
    if (lane == 0) rs[w] = s;
    __syncthreads();

    float rr[HH];
    #pragma unroll
    for (int h = 0; h < HH; h++) rr[h] = rs[h];

    float a0 = 0.f, a1 = 0.f, a2 = 0.f;
    #pragma unroll
    for (int h = 0; h < HH; h++) {
        a0 = fmaf(sm[h * NN + t],       rr[h], a0);
        a1 = fmaf(sm[h * NN + t + 384], rr[h], a1);
    }
    if (t < 16) {
        #pragma unroll
        for (int h = 0; h < HH; h++) a2 = fmaf(sm[h * NN + t + 768], rr[h], a2);
    }

    float mx = fmaxf(a0, a1);
    if (t < 16) mx = fmaxf(mx, a2);
    #pragma unroll
    for (int o = 16; o; o >>= 1) mx = fmaxf(mx, __shfl_xor_sync(0xffffffffu, mx, o));
    if (lane == 0) red[w] = mx;
    __syncthreads();
    if (t == 0) {
        float M = red[0];
        #pragma unroll
        for (int h = 1; h < HH; h++) M = fmaxf(M, red[h]);
        s_bcast = M;
    }
    __syncthreads();
    const float rowmax = s_bcast;

    __half* srow = g_scratch + (size_t)bi * NN;
    float e0 = expf(a0 - rowmax);
    float e1 = expf(a1 - rowmax);
    srow[t]       = __float2half_rn(e0);
    srow[t + 384] = __float2half_rn(e1);
    float sume = e0 + e1;
    if (t < 16) {
        float e2 = expf(a2 - rowmax);
        srow[t + 768] = __float2half_rn(e2);
        sume += e2;
    }
    #pragma unroll
    for (int o = 16; o; o >>= 1) sume += __shfl_xor_sync(0xffffffffu, sume, o);
    if (lane == 0) red[w] = sume;
    __syncthreads();
    if (t == 0) {
        float S = 0.f;
        #pragma unroll
        for (int h = 0; h < HH; h++) S += red[h];
        g_rowstats[bi] = make_float2(rowmax, S);
    }
}

// ---------------------------------------------------------------------------
// k_combine: one block per batch. 784 row stats -> gmax, 1/sum, row scales.
// ---------------------------------------------------------------------------
__global__ __launch_bounds__(256) void k_combine() {
    const int b = blockIdx.x;
    const int t = threadIdx.x;
    __shared__ float red[8];
    __shared__ float s_gmax, s_inv;

    float mx = -1e30f;
    for (int i = t; i < NN; i += 256) mx = fmaxf(mx, g_rowstats[b * NN + i].x);
    #pragma unroll
    for (int o = 16; o; o >>= 1) mx = fmaxf(mx, __shfl_xor_sync(0xffffffffu, mx, o));
    if ((t & 31) == 0) red[t >> 5] = mx;
    __syncthreads();
    if (t == 0) {
        float M = red[0];
        #pragma unroll
        for (int k = 1; k < 8; k++) M = fmaxf(M, red[k]);
        s_gmax = M;
    }
    __syncthreads();
    const float gmax = s_gmax;

    float s = 0.f;
    for (int i = t; i < NN; i += 256) {
        float2 st = g_rowstats[b * NN + i];
        s += st.y * expf(st.x - gmax);
    }
    #pragma unroll
    for (int o = 16; o; o >>= 1) s += __shfl_xor_sync(0xffffffffu, s, o);
    __syncthreads();
    if ((t & 31) == 0) red[t >> 5] = s;
    __syncthreads();
    if (t == 0) {
        float S = 0.f;
        #pragma unroll
        for (int k = 0; k < 8; k++) S += red[k];
        s_inv = 1.f / S;
    }
    __syncthreads();
    const float inv = s_inv;

    for (int i = t; i < NN; i += 256)
        g_rowscale[b * NN + i] = expf(g_rowstats[b * NN + i].x - gmax) * inv;
}

// ---------------------------------------------------------------------------
// k_norm: out = half2float(scratch) * rowscale[row].
// 4 independent int4 chains per thread (grid-stride) for MLP; 1201 blocks.
// ---------------------------------------------------------------------------
#define NORM_BLOCKS 1201
#define NORM_STRIDE (NORM_BLOCKS * 256)   // 307456

__global__ __launch_bounds__(256) void k_norm(float* __restrict__ out) {
    const int j0 = blockIdx.x * 256 + threadIdx.x;

    int   jj[4];
    int4  v[4];
    float sc[4];
    #pragma unroll
    for (int k = 0; k < 4; k++) {
        int j = j0 + k * NORM_STRIDE;
        jj[k] = j;
        if (j < NCHUNK) {
            v[k]  = ((const int4*)g_scratch)[j];
            sc[k] = g_rowscale[j / 98];          // 98 int4 per row
        }
    }
    #pragma unroll
    for (int k = 0; k < 4; k++) {
        int j = jj[k];
        if (j < NCHUNK) {
            float2 f0 = __half22float2(*(__half2*)&v[k].x);
            float2 f1 = __half22float2(*(__half2*)&v[k].y);
            float2 f2 = __half22float2(*(__half2*)&v[k].z);
            float2 f3 = __half22float2(*(__half2*)&v[k].w);
            float s = sc[k];
            float4 o0 = make_float4(f0.x * s, f0.y * s, f1.x * s, f1.y * s);
            float4 o1 = make_float4(f2.x * s, f2.y * s, f3.x * s, f3.y * s);
            ((float4*)out)[2 * j]     = o0;
            ((float4*)out)[2 * j + 1] = o1;
        }
    }
}

// ---------------------------------------------------------------------------
extern "C" void kernel_launch(void* const* d_in, const int* in_sizes, int n_in,
                              void* d_out, int out_size) {
    const float* m = (const float*)d_in[0];
    float* out = (float*)d_out;

    k_agg<<<NROWS, 384>>>(m);
    k_combine<<<BB, 256>>>();
    k_norm<<<NORM_BLOCKS, 256>>>(out);
}

// round 5
// speedup vs baseline: 1.2618x; 1.0946x over previous
#include <cuda_runtime.h>
#include <cuda_fp16.h>
#include <math.h>

#define BB 16
#define HH 12
#define NN 784
#define NROWS (BB * NN)        // 12544
#define NSQ (NN * NN)          // 614656

// Device-global scratch (allocation is forbidden; __device__ globals are allowed)
__device__ __half g_scratch[(size_t)BB * NSQ];   // exp(x - rowmax), ~19.7 MB
__device__ float2 g_rowstats[NROWS];             // (rowmax, rowsumexp)
__device__ float  g_rowscale[NROWS];             // exp(rowmax - gmax) / sum_b

// ---------------------------------------------------------------------------
// k_agg: one block per (b,i). 384 threads = 12 warps, warp w stages head w's
// row in SMEM + computes its rowsum. agg[l] = sum_h m[h][l]*rowsum[h] kept in
// registers; per-row max + exp + expsum computed in-block; exp written fp16.
// Input loads use __ldcs (evict-first): the 472 MB touch-once stream must not
// evict the 19.7 MB scratch from L2 (it is re-read by k_norm and overwritten
// next iteration; keeping it resident removes ~39 MB/iter of DRAM traffic).
// ---------------------------------------------------------------------------
__global__ __launch_bounds__(384) void k_agg(const float* __restrict__ m) {
    __shared__ float sm[HH * NN];   // 37632 B
    __shared__ float rs[HH];
    __shared__ float red[HH];
    __shared__ float s_bcast;

    const int bi = blockIdx.x;          // b*NN + i
    const int b  = bi / NN;
    const int i  = bi - b * NN;
    const int t    = threadIdx.x;
    const int w    = t >> 5;
    const int lane = t & 31;

    const float4* row = (const float4*)(m + ((size_t)(b * HH + w) * NN + i) * NN);
    float4* smrow = (float4*)(sm + w * NN);
    float s = 0.f;
    // 196 float4s per warp: 6 full rounds + 1 predicated (lane < 4)
    #pragma unroll
    for (int j = lane; j < NN / 4; j += 32) {
        float4 v = __ldcs(row + j);
        smrow[j] = v;
        s += (v.x + v.y) + (v.z + v.w);
    }
    #pragma unroll
    for (int o = 16; o; o >>= 1) s += __shfl_xor_sync(0xffffffffu, s, o);
    if (lane == 0) rs[w] = s;
    __syncthreads();

    float rr[HH];
    #pragma unroll
    for (int h = 0; h < HH; h++) rr[h] = rs[h];

    float a0 = 0.f, a1 = 0.f, a2 = 0.f;
    #pragma unroll
    for (int h = 0; h < HH; h++) {
        a0 = fmaf(sm[h * NN + t],       rr[h], a0);
        a1 = fmaf(sm[h * NN + t + 384], rr[h], a1);
    }
    if (t < 16) {
        #pragma unroll
        for (int h = 0; h < HH; h++) a2 = fmaf(sm[h * NN + t + 768], rr[h], a2);
    }

    float mx = fmaxf(a0, a1);
    if (t < 16) mx = fmaxf(mx, a2);
    #pragma unroll
    for (int o = 16; o; o >>= 1) mx = fmaxf(mx, __shfl_xor_sync(0xffffffffu, mx, o));
    if (lane == 0) red[w] = mx;
    __syncthreads();
    if (t == 0) {
        float M = red[0];
        #pragma unroll
        for (int h = 1; h < HH; h++) M = fmaxf(M, red[h]);
        s_bcast = M;
    }
    __syncthreads();
    const float rowmax = s_bcast;

    __half* srow = g_scratch + (size_t)bi * NN;
    float e0 = expf(a0 - rowmax);
    float e1 = expf(a1 - rowmax);
    srow[t]       = __float2half_rn(e0);
    srow[t + 384] = __float2half_rn(e1);
    float sume = e0 + e1;
    if (t < 16) {
        float e2 = expf(a2 - rowmax);
        srow[t + 768] = __float2half_rn(e2);
        sume += e2;
    }
    #pragma unroll
    for (int o = 16; o; o >>= 1) sume += __shfl_xor_sync(0xffffffffu, sume, o);
    if (lane == 0) red[w] = sume;
    __syncthreads();
    if (t == 0) {
        float S = 0.f;
        #pragma unroll
        for (int h = 0; h < HH; h++) S += red[h];
        g_rowstats[bi] = make_float2(rowmax, S);
    }
}

// ---------------------------------------------------------------------------
// k_combine: one block per batch. 784 row stats -> gmax, 1/sum, row scales.
// ---------------------------------------------------------------------------
__global__ __launch_bounds__(256) void k_combine() {
    const int b = blockIdx.x;
    const int t = threadIdx.x;
    __shared__ float red[8];
    __shared__ float s_gmax, s_inv;

    float mx = -1e30f;
    for (int i = t; i < NN; i += 256) mx = fmaxf(mx, g_rowstats[b * NN + i].x);
    #pragma unroll
    for (int o = 16; o; o >>= 1) mx = fmaxf(mx, __shfl_xor_sync(0xffffffffu, mx, o));
    if ((t & 31) == 0) red[t >> 5] = mx;
    __syncthreads();
    if (t == 0) {
        float M = red[0];
        #pragma unroll
        for (int k = 1; k < 8; k++) M = fmaxf(M, red[k]);
        s_gmax = M;
    }
    __syncthreads();
    const float gmax = s_gmax;

    float s = 0.f;
    for (int i = t; i < NN; i += 256) {
        float2 st = g_rowstats[b * NN + i];
        s += st.y * expf(st.x - gmax);
    }
    #pragma unroll
    for (int o = 16; o; o >>= 1) s += __shfl_xor_sync(0xffffffffu, s, o);
    __syncthreads();
    if ((t & 31) == 0) red[t >> 5] = s;
    __syncthreads();
    if (t == 0) {
        float S = 0.f;
        #pragma unroll
        for (int k = 0; k < 8; k++) S += red[k];
        s_inv = 1.f / S;
    }
    __syncthreads();
    const float inv = s_inv;

    for (int i = t; i < NN; i += 256)
        g_rowscale[b * NN + i] = expf(g_rowstats[b * NN + i].x - gmax) * inv;
}

// ---------------------------------------------------------------------------
// k_norm: out[bi][l] = half2float(scratch[bi][l]) * rowscale[bi]
// (R2-proven simple form.) Scratch reads should now be L2 hits.
// Total int4 = 16*614656/8 = 1,229,312 = 4802 blocks * 256 exactly.
// ---------------------------------------------------------------------------
__global__ __launch_bounds__(256) void k_norm(float* __restrict__ out) {
    const int j = blockIdx.x * 256 + threadIdx.x;   // int4 index
    const int row = j / 98;                          // 98 int4 per row (784/8)
    const float sc = g_rowscale[row];

    int4 v = ((const int4*)g_scratch)[j];
    float2 f0 = __half22float2(*(__half2*)&v.x);
    float2 f1 = __half22float2(*(__half2*)&v.y);
    float2 f2 = __half22float2(*(__half2*)&v.z);
    float2 f3 = __half22float2(*(__half2*)&v.w);

    float4 o0 = make_float4(f0.x * sc, f0.y * sc, f1.x * sc, f1.y * sc);
    float4 o1 = make_float4(f2.x * sc, f2.y * sc, f3.x * sc, f3.y * sc);
    ((float4*)out)[2 * j]     = o0;
    ((float4*)out)[2 * j + 1] = o1;
}

// ---------------------------------------------------------------------------
extern "C" void kernel_launch(void* const* d_in, const int* in_sizes, int n_in,
                              void* d_out, int out_size) {
    const float* m = (const float*)d_in[0];
    float* out = (float*)d_out;

    k_agg<<<NROWS, 384>>>(m);
    k_combine<<<BB, 256>>>();
    k_norm<<<4802, 256>>>(out);
}